// round 1
// baseline (speedup 1.0000x reference)
#include <cuda_runtime.h>
#include <math.h>

#define BATCH 65536
#define DIN 256
#define DH 512
#define DOUT 128

// Scratch (no cudaMalloc allowed): mx1 / h1 in-place, and mx2.
__device__ float g_h[(size_t)BATCH * DH];     // 128 MiB
__device__ float g_o[(size_t)BATCH * DOUT];   //  32 MiB

__device__ __forceinline__ float artanh_cl(float z) {
    z = fminf(fmaxf(z, -1.0f + 1e-7f), 1.0f - 1e-7f);
    return atanhf(z);
}

// Block-wide sum, result broadcast to all threads. 256 threads = 8 warps.
__device__ __forceinline__ float block_reduce_sum(float v, float* sbuf) {
    const int tid = threadIdx.x;
    #pragma unroll
    for (int o = 16; o > 0; o >>= 1) v += __shfl_xor_sync(0xffffffffu, v, o);
    if ((tid & 31) == 0) sbuf[tid >> 5] = v;
    __syncthreads();
    if (tid < 32) {
        float x = (tid < 8) ? sbuf[tid] : 0.0f;
        #pragma unroll
        for (int o = 4; o > 0; o >>= 1) x += __shfl_xor_sync(0xffffffffu, x, o);
        if (tid == 0) sbuf[0] = x;
    }
    __syncthreads();
    float r = sbuf[0];
    __syncthreads();   // safe for sbuf reuse
    return r;
}

// C[m,n] = sum_k A[m*K+k] * B[n*K+k]   (both operands K-contiguous)
// BM=BN=128, BK=16, 256 threads, 8x8 per-thread tile.
template<int K, int N>
__global__ void __launch_bounds__(256) sgemm_nt(const float* __restrict__ A,
                                                const float* __restrict__ B,
                                                float* __restrict__ C)
{
    constexpr int BM = 128, BN = 128, BK = 16;
    __shared__ float As[BK][BM + 4];   // stride 132 floats -> 16B-aligned rows
    __shared__ float Bs[BK][BN + 4];
    const int tid = threadIdx.x;
    const int tx = tid & 15, ty = tid >> 4;
    const int bm = blockIdx.y * BM;
    const int bn = blockIdx.x * BN;

    float acc[8][8];
    #pragma unroll
    for (int i = 0; i < 8; i++)
        #pragma unroll
        for (int j = 0; j < 8; j++) acc[i][j] = 0.0f;

    for (int k0 = 0; k0 < K; k0 += BK) {
        #pragma unroll
        for (int l = 0; l < 2; l++) {
            int id  = tid + l * 256;         // float4 id, 0..511
            int row = id >> 2;               // 0..127
            int c4  = (id & 3) << 2;         // 0,4,8,12
            float4 va = *reinterpret_cast<const float4*>(&A[(size_t)(bm + row) * K + k0 + c4]);
            As[c4 + 0][row] = va.x; As[c4 + 1][row] = va.y;
            As[c4 + 2][row] = va.z; As[c4 + 3][row] = va.w;
            float4 vb = *reinterpret_cast<const float4*>(&B[(size_t)(bn + row) * K + k0 + c4]);
            Bs[c4 + 0][row] = vb.x; Bs[c4 + 1][row] = vb.y;
            Bs[c4 + 2][row] = vb.z; Bs[c4 + 3][row] = vb.w;
        }
        __syncthreads();
        #pragma unroll
        for (int k = 0; k < BK; k++) {
            float ra[8], rb[8];
            *reinterpret_cast<float4*>(&ra[0]) = *reinterpret_cast<const float4*>(&As[k][ty * 8]);
            *reinterpret_cast<float4*>(&ra[4]) = *reinterpret_cast<const float4*>(&As[k][ty * 8 + 4]);
            *reinterpret_cast<float4*>(&rb[0]) = *reinterpret_cast<const float4*>(&Bs[k][tx * 8]);
            *reinterpret_cast<float4*>(&rb[4]) = *reinterpret_cast<const float4*>(&Bs[k][tx * 8 + 4]);
            #pragma unroll
            for (int i = 0; i < 8; i++)
                #pragma unroll
                for (int j = 0; j < 8; j++)
                    acc[i][j] = fmaf(ra[i], rb[j], acc[i][j]);
        }
        __syncthreads();
    }

    #pragma unroll
    for (int i = 0; i < 8; i++) {
        const size_t m = (size_t)(bm + ty * 8 + i);
        #pragma unroll
        for (int j = 0; j < 8; j += 4) {
            float4 v = make_float4(acc[i][j], acc[i][j + 1], acc[i][j + 2], acc[i][j + 3]);
            *reinterpret_cast<float4*>(&C[m * N + bn + tx * 8 + j]) = v;
        }
    }
}

// Layer-1 epilogue, in-place on g_h (mx1 -> h1):
// mobius_matvec tail -> project -> mobius_add(b1) -> project
// -> expmap0(tanh(logmap0(.))) -> project
__global__ void __launch_bounds__(256) ew1_kernel(const float* __restrict__ x,
                                                  const float* __restrict__ b)
{
    __shared__ float sbuf[32];
    const int r = blockIdx.x;
    const int t = threadIdx.x;
    const float maxn = 1.0f - 4e-3f;
    float* h = g_h + (size_t)r * DH;

    // ||x|| over 256 elements
    float xv  = x[(size_t)r * DIN + t];
    float xn2 = block_reduce_sum(xv * xv, sbuf);

    float v0 = h[t], v1 = h[t + 256];
    float mxn2 = block_reduce_sum(v0 * v0 + v1 * v1, sbuf);

    float xn  = fmaxf(sqrtf(xn2),  1e-15f);
    float mxn = fmaxf(sqrtf(mxn2), 1e-15f);
    float s = tanhf(mxn / xn * artanh_cl(xn)) / mxn;
    v0 *= s; v1 *= s;

    // project
    float n2 = block_reduce_sum(v0 * v0 + v1 * v1, sbuf);
    float n  = fmaxf(sqrtf(n2), 1e-15f);
    float x2;
    if (n > maxn) { float f = maxn / n; v0 *= f; v1 *= f; x2 = maxn * maxn; }
    else          { x2 = n2; }

    // mobius_add(h, b1)
    float b0 = b[t], b1v = b[t + 256];
    float xy = block_reduce_sum(v0 * b0 + v1 * b1v, sbuf);
    float y2 = block_reduce_sum(b0 * b0 + b1v * b1v, sbuf);
    float den = fmaxf(1.0f + 2.0f * xy + x2 * y2, 1e-15f);
    float ch = (1.0f + 2.0f * xy + y2) / den;
    float cb = (1.0f - x2) / den;
    v0 = ch * v0 + cb * b0;
    v1 = ch * v1 + cb * b1v;

    // project
    n2 = block_reduce_sum(v0 * v0 + v1 * v1, sbuf);
    n  = fmaxf(sqrtf(n2), 1e-15f);
    if (n > maxn) { float f = maxn / n; v0 *= f; v1 *= f; n = maxn; }

    // logmap0 + tanh
    float a = artanh_cl(n) / n;
    v0 = tanhf(v0 * a);
    v1 = tanhf(v1 * a);

    // expmap0
    n2 = block_reduce_sum(v0 * v0 + v1 * v1, sbuf);
    n  = fmaxf(sqrtf(n2), 1e-15f);
    float tn = tanhf(n);
    float e  = tn / n;
    v0 *= e; v1 *= e;

    // final project: ||result|| = tanh(n) analytically
    if (tn > maxn) { float f = maxn / tn; v0 *= f; v1 *= f; }

    h[t] = v0; h[t + 256] = v1;
}

// Layer-2 epilogue: mobius_matvec tail -> project -> mobius_add(b2) -> project -> out
__global__ void __launch_bounds__(256) ew2_kernel(const float* __restrict__ b,
                                                  float* __restrict__ out)
{
    __shared__ float sbuf[32];
    const int r = blockIdx.x;
    const int t = threadIdx.x;
    const float maxn = 1.0f - 4e-3f;
    const float* hrow = g_h + (size_t)r * DH;

    float h0 = hrow[t], h1 = hrow[t + 256];
    float xn2 = block_reduce_sum(h0 * h0 + h1 * h1, sbuf);

    float v = (t < DOUT) ? g_o[(size_t)r * DOUT + t] : 0.0f;
    float mxn2 = block_reduce_sum(v * v, sbuf);

    float xn  = fmaxf(sqrtf(xn2),  1e-15f);
    float mxn = fmaxf(sqrtf(mxn2), 1e-15f);
    float s = tanhf(mxn / xn * artanh_cl(xn)) / mxn;
    v *= s;

    float n2 = block_reduce_sum(v * v, sbuf);
    float n  = fmaxf(sqrtf(n2), 1e-15f);
    float x2;
    if (n > maxn) { float f = maxn / n; v *= f; x2 = maxn * maxn; }
    else          { x2 = n2; }

    float bv = (t < DOUT) ? b[t] : 0.0f;
    float xy = block_reduce_sum(v * bv, sbuf);
    float y2 = block_reduce_sum(bv * bv, sbuf);
    float den = fmaxf(1.0f + 2.0f * xy + x2 * y2, 1e-15f);
    float ch = (1.0f + 2.0f * xy + y2) / den;
    float cb = (1.0f - x2) / den;
    v = ch * v + cb * bv;

    n2 = block_reduce_sum(v * v, sbuf);
    n  = fmaxf(sqrtf(n2), 1e-15f);
    if (n > maxn) v *= maxn / n;

    if (t < DOUT) out[(size_t)r * DOUT + t] = v;
}

extern "C" void kernel_launch(void* const* d_in, const int* in_sizes, int n_in,
                              void* d_out, int out_size)
{
    const float* x  = (const float*)d_in[0];
    const float* W1 = (const float*)d_in[1];
    const float* b1 = (const float*)d_in[2];
    const float* W2 = (const float*)d_in[3];
    const float* b2 = (const float*)d_in[4];
    float* out = (float*)d_out;

    float *gh, *go;
    cudaGetSymbolAddress((void**)&gh, g_h);
    cudaGetSymbolAddress((void**)&go, g_o);

    // mx1 = x @ W1^T   [65536,512]
    sgemm_nt<DIN, DH><<<dim3(DH / 128, BATCH / 128), 256>>>(x, W1, gh);
    // layer-1 hyperbolic epilogue + mobius-tanh, in place
    ew1_kernel<<<BATCH, 256>>>(x, b1);
    // mx2 = h1 @ W2^T  [65536,128]
    sgemm_nt<DH, DOUT><<<dim3(DOUT / 128, BATCH / 128), 256>>>(gh, W2, go);
    // layer-2 epilogue -> d_out
    ew2_kernel<<<BATCH, 256>>>(b2, out);
}

// round 4
// speedup vs baseline: 2.4914x; 2.4914x over previous
#include <cuda_runtime.h>
#include <cuda_bf16.h>
#include <stdint.h>
#include <math.h>

#define BATCH 65536
#define DIN 256
#define DH 512
#define DOUT 128

// ---------------- scratch (__device__ globals; no cudaMalloc allowed) ----------------
__device__ __nv_bfloat16 g_xhi[(size_t)BATCH * DIN];
__device__ __nv_bfloat16 g_xlo[(size_t)BATCH * DIN];
__device__ __nv_bfloat16 g_w1hi[DH * DIN], g_w1lo[DH * DIN];
__device__ __nv_bfloat16 g_w2hi[DOUT * DH], g_w2lo[DOUT * DH];
__device__ __nv_bfloat16 g_hhi[(size_t)BATCH * DH];
__device__ __nv_bfloat16 g_hlo[(size_t)BATCH * DH];
__device__ float g_c[(size_t)BATCH * DH];          // fp32 GEMM output (reused by both layers)
__device__ float g_xn2[BATCH], g_hn2[BATCH];

__device__ __forceinline__ float artanh_cl(float z) {
    z = fminf(fmaxf(z, -1.0f + 1e-7f), 1.0f - 1e-7f);
    return atanhf(z);
}
__device__ __forceinline__ float wred(float v) {
    #pragma unroll
    for (int o = 16; o > 0; o >>= 1) v += __shfl_xor_sync(0xffffffffu, v, o);
    return v;
}
__device__ __forceinline__ uint32_t smem_u32(const void* p) {
    uint32_t a;
    asm("{ .reg .u64 t; cvta.to.shared.u64 t, %1; cvt.u32.u64 %0, t; }" : "=r"(a) : "l"(p));
    return a;
}

#define LDSM4(r0, r1, r2, r3, addr)                                               \
    asm volatile("ldmatrix.sync.aligned.m8n8.x4.shared.b16 {%0,%1,%2,%3}, [%4];"  \
                 : "=r"(r0), "=r"(r1), "=r"(r2), "=r"(r3) : "r"(addr))

#define MMA16816(c, a, b)                                                          \
    asm volatile("mma.sync.aligned.m16n8k16.row.col.f32.bf16.bf16.f32 "            \
                 "{%0,%1,%2,%3}, {%4,%5,%6,%7}, {%8,%9}, {%0,%1,%2,%3};"           \
                 : "+f"((c)[0]), "+f"((c)[1]), "+f"((c)[2]), "+f"((c)[3])          \
                 : "r"((a)[0]), "r"((a)[1]), "r"((a)[2]), "r"((a)[3]),             \
                   "r"((b)[0]), "r"((b)[1]))

// ---------------- conversion kernels ----------------
__global__ void __launch_bounds__(256) convert_x_kernel(const float* __restrict__ x) {
    int gw = (blockIdx.x * 256 + threadIdx.x) >> 5;   // row
    int lane = threadIdx.x & 31;
    const float4* xr = reinterpret_cast<const float4*>(x + (size_t)gw * DIN);
    float s2 = 0.f;
    #pragma unroll
    for (int i = 0; i < 2; i++) {
        int q = lane + 32 * i;                        // float4 index 0..63
        float4 v = xr[q];
        s2 += v.x * v.x + v.y * v.y + v.z * v.z + v.w * v.w;
        __nv_bfloat16 h0 = __float2bfloat16(v.x), h1 = __float2bfloat16(v.y);
        __nv_bfloat16 h2 = __float2bfloat16(v.z), h3 = __float2bfloat16(v.w);
        __nv_bfloat16 l0 = __float2bfloat16(v.x - __bfloat162float(h0));
        __nv_bfloat16 l1 = __float2bfloat16(v.y - __bfloat162float(h1));
        __nv_bfloat16 l2 = __float2bfloat16(v.z - __bfloat162float(h2));
        __nv_bfloat16 l3 = __float2bfloat16(v.w - __bfloat162float(h3));
        __nv_bfloat162* dh = reinterpret_cast<__nv_bfloat162*>(g_xhi) + ((size_t)gw * DIN >> 1) + q * 2;
        __nv_bfloat162* dl = reinterpret_cast<__nv_bfloat162*>(g_xlo) + ((size_t)gw * DIN >> 1) + q * 2;
        __nv_bfloat162 th; th.x = h0; th.y = h1; dh[0] = th;
        th.x = h2; th.y = h3; dh[1] = th;
        __nv_bfloat162 tl; tl.x = l0; tl.y = l1; dl[0] = tl;
        tl.x = l2; tl.y = l3; dl[1] = tl;
    }
    s2 = wred(s2);
    if (lane == 0) g_xn2[gw] = s2;
}

__global__ void __launch_bounds__(256) convert_w_kernel(const float* __restrict__ W1,
                                                        const float* __restrict__ W2) {
    int i = blockIdx.x * 256 + threadIdx.x;
    if (i < DH * DIN) {
        float v = W1[i];
        __nv_bfloat16 h = __float2bfloat16(v);
        g_w1hi[i] = h;
        g_w1lo[i] = __float2bfloat16(v - __bfloat162float(h));
    }
    if (i < DOUT * DH) {
        float v = W2[i];
        __nv_bfloat16 h = __float2bfloat16(v);
        g_w2hi[i] = h;
        g_w2lo[i] = __float2bfloat16(v - __bfloat162float(h));
    }
}

// ---------------- mma.sync split-bf16 GEMM ----------------
// C[m,n] = sum_k A[m,k]*B[n,k] with A ~ Ahi+Alo, B ~ Bhi+Blo (3-term product).
// BM=128, BN=64, BK=32. 256 threads = 8 warps (4 in M x 2 in N), warp tile 32x32.
template<int K, int N>
__global__ void __launch_bounds__(256) mma_gemm(const __nv_bfloat16* __restrict__ Ahi,
                                                const __nv_bfloat16* __restrict__ Alo,
                                                const __nv_bfloat16* __restrict__ Bhi,
                                                const __nv_bfloat16* __restrict__ Blo,
                                                float* __restrict__ C)
{
    constexpr int LDS = 40;                 // padded row stride (elements)
    __shared__ __nv_bfloat16 sAhi[128 * LDS], sAlo[128 * LDS];
    __shared__ __nv_bfloat16 sBhi[64 * LDS], sBlo[64 * LDS];

    const int tid = threadIdx.x, lane = tid & 31, wid = tid >> 5;
    const int warpM = wid & 3, warpN = wid >> 2;
    const int bm = blockIdx.y * 128, bn = blockIdx.x * 64;

    float acc[2][4][4];
    #pragma unroll
    for (int i = 0; i < 2; i++)
        #pragma unroll
        for (int j = 0; j < 4; j++)
            #pragma unroll
            for (int l = 0; l < 4; l++) acc[i][j][l] = 0.f;

    // ldmatrix lane addressing
    const int rowA = (lane & 7) + ((lane >> 3) & 1) * 8;    // 0..15
    const int colA = ((lane >> 4) & 1) * 8;                 // 0 or 8
    const int rowB = warpN * 32 + ((lane >> 4) & 1) * 8 + (lane & 7);
    const int colB = ((lane >> 3) & 1) * 8;

    const uint32_t uAhi = smem_u32(sAhi), uAlo = smem_u32(sAlo);
    const uint32_t uBhi = smem_u32(sBhi), uBlo = smem_u32(sBlo);

    for (int k0 = 0; k0 < K; k0 += 32) {
        __syncthreads();
        // load A tiles: 128x32 (512 uint4), 2 per thread, hi+lo
        #pragma unroll
        for (int l = 0; l < 2; l++) {
            int j = tid + l * 256;
            int r = j >> 2, q = (j & 3) << 3;
            *reinterpret_cast<uint4*>(&sAhi[r * LDS + q]) =
                *reinterpret_cast<const uint4*>(&Ahi[(size_t)(bm + r) * K + k0 + q]);
            *reinterpret_cast<uint4*>(&sAlo[r * LDS + q]) =
                *reinterpret_cast<const uint4*>(&Alo[(size_t)(bm + r) * K + k0 + q]);
        }
        // load B tiles: 64x32 (256 uint4), 1 per thread, hi+lo
        {
            int r = tid >> 2, q = (tid & 3) << 3;
            *reinterpret_cast<uint4*>(&sBhi[r * LDS + q]) =
                *reinterpret_cast<const uint4*>(&Bhi[(size_t)(bn + r) * K + k0 + q]);
            *reinterpret_cast<uint4*>(&sBlo[r * LDS + q]) =
                *reinterpret_cast<const uint4*>(&Blo[(size_t)(bn + r) * K + k0 + q]);
        }
        __syncthreads();

        #pragma unroll
        for (int ks = 0; ks < 32; ks += 16) {
            uint32_t ahi[2][4], alo[2][4], bhi[4][2], blo[4][2];
            #pragma unroll
            for (int mt = 0; mt < 2; mt++) {
                uint32_t off = ((warpM * 32 + mt * 16 + rowA) * LDS + colA + ks) * 2;
                LDSM4(ahi[mt][0], ahi[mt][1], ahi[mt][2], ahi[mt][3], uAhi + off);
                LDSM4(alo[mt][0], alo[mt][1], alo[mt][2], alo[mt][3], uAlo + off);
            }
            #pragma unroll
            for (int p = 0; p < 2; p++) {
                uint32_t off = ((rowB + p * 16) * LDS + colB + ks) * 2;
                LDSM4(bhi[2 * p][0], bhi[2 * p][1], bhi[2 * p + 1][0], bhi[2 * p + 1][1], uBhi + off);
                LDSM4(blo[2 * p][0], blo[2 * p][1], blo[2 * p + 1][0], blo[2 * p + 1][1], uBlo + off);
            }
            #pragma unroll
            for (int mt = 0; mt < 2; mt++)
                #pragma unroll
                for (int nt = 0; nt < 4; nt++) {
                    MMA16816(acc[mt][nt], ahi[mt], bhi[nt]);
                    MMA16816(acc[mt][nt], alo[mt], bhi[nt]);
                    MMA16816(acc[mt][nt], ahi[mt], blo[nt]);
                }
        }
    }

    // writeout
    #pragma unroll
    for (int mt = 0; mt < 2; mt++) {
        int r0 = bm + warpM * 32 + mt * 16 + (lane >> 2);
        #pragma unroll
        for (int nt = 0; nt < 4; nt++) {
            int c = bn + warpN * 32 + nt * 8 + (lane & 3) * 2;
            float2 v0 = make_float2(acc[mt][nt][0], acc[mt][nt][1]);
            float2 v1 = make_float2(acc[mt][nt][2], acc[mt][nt][3]);
            *reinterpret_cast<float2*>(&C[(size_t)r0 * N + c]) = v0;
            *reinterpret_cast<float2*>(&C[(size_t)(r0 + 8) * N + c]) = v1;
        }
    }
}

// ---------------- layer-1 elementwise: warp per row, shfl-only ----------------
// in: g_c = mx1 [B, 512]; out: g_hhi/g_hlo bf16 splits + g_hn2
__global__ void __launch_bounds__(256) ew1_warp(const float* __restrict__ b1) {
    const int wid = threadIdx.x >> 5, lane = threadIdx.x & 31;
    const int row = blockIdx.x * 8 + wid;
    const float maxn = 1.0f - 4e-3f;
    const float* mx = g_c + (size_t)row * DH;

    float mv[16], bv[16];
    const float4* m4 = reinterpret_cast<const float4*>(mx);
    const float4* b4 = reinterpret_cast<const float4*>(b1);
    #pragma unroll
    for (int i = 0; i < 4; i++) {
        float4 a = m4[lane * 4 + i];
        mv[4 * i] = a.x; mv[4 * i + 1] = a.y; mv[4 * i + 2] = a.z; mv[4 * i + 3] = a.w;
        float4 b = b4[lane * 4 + i];
        bv[4 * i] = b.x; bv[4 * i + 1] = b.y; bv[4 * i + 2] = b.z; bv[4 * i + 3] = b.w;
    }
    float pm = 0.f, pvb = 0.f, py = 0.f;
    #pragma unroll
    for (int i = 0; i < 16; i++) {
        pm  = fmaf(mv[i], mv[i], pm);
        pvb = fmaf(mv[i], bv[i], pvb);
        py  = fmaf(bv[i], bv[i], py);
    }
    float mxn2 = wred(pm), vb = wred(pvb), y2 = wred(py);

    float xn  = fmaxf(sqrtf(g_xn2[row]), 1e-15f);
    float mxn = fmaxf(sqrtf(mxn2), 1e-15f);
    float ns  = tanhf(mxn / xn * artanh_cl(xn));
    float s   = ns / mxn;
    float f1  = ns > maxn ? maxn / ns : 1.f;
    float sc1 = s * f1;
    float ncl = fminf(ns, maxn);
    float x2  = ncl * ncl;
    float xy  = sc1 * vb;
    float den = fmaxf(1.f + 2.f * xy + x2 * y2, 1e-15f);
    float chv = (1.f + 2.f * xy + y2) / den;
    float cb  = (1.f - x2) / den;
    float al  = chv * sc1, be = cb;
    float np2 = al * al * mxn2 + 2.f * al * be * vb + be * be * y2;
    float np  = fmaxf(sqrtf(np2), 1e-15f);
    float f2  = np > maxn ? maxn / np : 1.f;
    float nn  = fminf(np, maxn);
    float gg  = artanh_cl(nn) / nn * f2;

    float w[16], pw = 0.f;
    #pragma unroll
    for (int i = 0; i < 16; i++) {
        w[i] = tanhf(gg * fmaf(al, mv[i], be * bv[i]));
        pw = fmaf(w[i], w[i], pw);
    }
    float wn2 = wred(pw);
    float wn = fmaxf(sqrtf(wn2), 1e-15f);
    float tn = tanhf(wn);
    float hc = fminf(tn, maxn);
    float e3 = hc / wn;
    if (lane == 0) g_hn2[row] = hc * hc;

    uint32_t ph[8], pl[8];
    #pragma unroll
    for (int i = 0; i < 8; i++) {
        float v0 = e3 * w[2 * i], v1 = e3 * w[2 * i + 1];
        __nv_bfloat16 h0 = __float2bfloat16(v0), h1 = __float2bfloat16(v1);
        __nv_bfloat16 l0 = __float2bfloat16(v0 - __bfloat162float(h0));
        __nv_bfloat16 l1 = __float2bfloat16(v1 - __bfloat162float(h1));
        ph[i] = (uint32_t)__bfloat16_as_ushort(h0) | ((uint32_t)__bfloat16_as_ushort(h1) << 16);
        pl[i] = (uint32_t)__bfloat16_as_ushort(l0) | ((uint32_t)__bfloat16_as_ushort(l1) << 16);
    }
    uint4* dh = reinterpret_cast<uint4*>(g_hhi + (size_t)row * DH + lane * 16);
    uint4* dl = reinterpret_cast<uint4*>(g_hlo + (size_t)row * DH + lane * 16);
    dh[0] = make_uint4(ph[0], ph[1], ph[2], ph[3]);
    dh[1] = make_uint4(ph[4], ph[5], ph[6], ph[7]);
    dl[0] = make_uint4(pl[0], pl[1], pl[2], pl[3]);
    dl[1] = make_uint4(pl[4], pl[5], pl[6], pl[7]);
}

// ---------------- layer-2 elementwise: warp per row ----------------
__global__ void __launch_bounds__(256) ew2_warp(const float* __restrict__ b2,
                                                float* __restrict__ out) {
    const int wid = threadIdx.x >> 5, lane = threadIdx.x & 31;
    const int row = blockIdx.x * 8 + wid;
    const float maxn = 1.0f - 4e-3f;
    const float* mx = g_c + (size_t)row * DOUT;

    float4 a = reinterpret_cast<const float4*>(mx)[lane];
    float4 b = reinterpret_cast<const float4*>(b2)[lane];
    float mv[4] = {a.x, a.y, a.z, a.w};
    float bv[4] = {b.x, b.y, b.z, b.w};
    float pm = 0.f, pvb = 0.f, py = 0.f;
    #pragma unroll
    for (int i = 0; i < 4; i++) {
        pm  = fmaf(mv[i], mv[i], pm);
        pvb = fmaf(mv[i], bv[i], pvb);
        py  = fmaf(bv[i], bv[i], py);
    }
    float mxn2 = wred(pm), vb = wred(pvb), y2 = wred(py);

    float xn  = fmaxf(sqrtf(g_hn2[row]), 1e-15f);
    float mxn = fmaxf(sqrtf(mxn2), 1e-15f);
    float ns  = tanhf(mxn / xn * artanh_cl(xn));
    float s   = ns / mxn;
    float f1  = ns > maxn ? maxn / ns : 1.f;
    float sc1 = s * f1;
    float ncl = fminf(ns, maxn);
    float x2  = ncl * ncl;
    float xy  = sc1 * vb;
    float den = fmaxf(1.f + 2.f * xy + x2 * y2, 1e-15f);
    float chv = (1.f + 2.f * xy + y2) / den;
    float cb  = (1.f - x2) / den;
    float al  = chv * sc1, be = cb;
    float np2 = al * al * mxn2 + 2.f * al * be * vb + be * be * y2;
    float np  = fmaxf(sqrtf(np2), 1e-15f);
    float f2  = np > maxn ? maxn / np : 1.f;

    float4 o;
    o.x = f2 * fmaf(al, mv[0], be * bv[0]);
    o.y = f2 * fmaf(al, mv[1], be * bv[1]);
    o.z = f2 * fmaf(al, mv[2], be * bv[2]);
    o.w = f2 * fmaf(al, mv[3], be * bv[3]);
    reinterpret_cast<float4*>(out + (size_t)row * DOUT)[lane] = o;
}

// ---------------- launch ----------------
extern "C" void kernel_launch(void* const* d_in, const int* in_sizes, int n_in,
                              void* d_out, int out_size) {
    const float* x  = (const float*)d_in[0];
    const float* W1 = (const float*)d_in[1];
    const float* b1 = (const float*)d_in[2];
    const float* W2 = (const float*)d_in[3];
    const float* b2 = (const float*)d_in[4];
    float* out = (float*)d_out;

    __nv_bfloat16 *xhi, *xlo, *w1hi, *w1lo, *w2hi, *w2lo, *hhi, *hlo;
    float* c;
    cudaGetSymbolAddress((void**)&xhi, g_xhi);
    cudaGetSymbolAddress((void**)&xlo, g_xlo);
    cudaGetSymbolAddress((void**)&w1hi, g_w1hi);
    cudaGetSymbolAddress((void**)&w1lo, g_w1lo);
    cudaGetSymbolAddress((void**)&w2hi, g_w2hi);
    cudaGetSymbolAddress((void**)&w2lo, g_w2lo);
    cudaGetSymbolAddress((void**)&hhi, g_hhi);
    cudaGetSymbolAddress((void**)&hlo, g_hlo);
    cudaGetSymbolAddress((void**)&c, g_c);

    convert_x_kernel<<<BATCH / 8, 256>>>(x);
    convert_w_kernel<<<(DH * DIN + 255) / 256, 256>>>(W1, W2);

    // layer 1: mx1 = x @ W1^T  [B, 512]
    mma_gemm<DIN, DH><<<dim3(DH / 64, BATCH / 128), 256>>>(xhi, xlo, w1hi, w1lo, c);
    ew1_warp<<<BATCH / 8, 256>>>(b1);

    // layer 2: mx2 = h @ W2^T  [B, 128]
    mma_gemm<DH, DOUT><<<dim3(DOUT / 64, BATCH / 128), 256>>>(hhi, hlo, w2hi, w2lo, c);
    ew2_warp<<<BATCH / 8, 256>>>(b2, out);
}

// round 5
// speedup vs baseline: 2.8368x; 1.1386x over previous
#include <cuda_runtime.h>
#include <cuda_bf16.h>
#include <stdint.h>
#include <math.h>

#define BATCH 65536
#define DIN 256
#define DH 512
#define DOUT 128

// ---------------- scratch (__device__ globals; no cudaMalloc allowed) ----------------
__device__ __nv_bfloat16 g_xhi[(size_t)BATCH * DIN];
__device__ __nv_bfloat16 g_xlo[(size_t)BATCH * DIN];
__device__ __nv_bfloat16 g_w1hi[DH * DIN], g_w1lo[DH * DIN];
__device__ __nv_bfloat16 g_w2hi[DOUT * DH], g_w2lo[DOUT * DH];
__device__ __nv_bfloat16 g_hhi[(size_t)BATCH * DH];
__device__ __nv_bfloat16 g_hlo[(size_t)BATCH * DH];
__device__ float g_c[(size_t)BATCH * DH];          // fp32 GEMM output (reused by both layers)
__device__ float g_xn2[BATCH], g_hn2[BATCH];

__device__ __forceinline__ float artanh_fast(float z) {
    z = fminf(fmaxf(z, -1.0f + 1e-7f), 1.0f - 1e-7f);
    return 0.5f * __logf((1.0f + z) / (1.0f - z));
}
__device__ __forceinline__ float tanh_fast(float x) {
    float ax = fabsf(x);
    float t = __expf(-2.0f * ax);
    float r = (1.0f - t) / (1.0f + t);
    return copysignf(r, x);
}
__device__ __forceinline__ float wred(float v) {
    #pragma unroll
    for (int o = 16; o > 0; o >>= 1) v += __shfl_xor_sync(0xffffffffu, v, o);
    return v;
}
__device__ __forceinline__ uint32_t smem_u32(const void* p) {
    uint32_t a;
    asm("{ .reg .u64 t; cvta.to.shared.u64 t, %1; cvt.u32.u64 %0, t; }" : "=r"(a) : "l"(p));
    return a;
}

#define LDSM4(r0, r1, r2, r3, addr)                                               \
    asm volatile("ldmatrix.sync.aligned.m8n8.x4.shared.b16 {%0,%1,%2,%3}, [%4];"  \
                 : "=r"(r0), "=r"(r1), "=r"(r2), "=r"(r3) : "r"(addr))

#define MMA16816(c, a, b)                                                          \
    asm volatile("mma.sync.aligned.m16n8k16.row.col.f32.bf16.bf16.f32 "            \
                 "{%0,%1,%2,%3}, {%4,%5,%6,%7}, {%8,%9}, {%0,%1,%2,%3};"           \
                 : "+f"((c)[0]), "+f"((c)[1]), "+f"((c)[2]), "+f"((c)[3])          \
                 : "r"((a)[0]), "r"((a)[1]), "r"((a)[2]), "r"((a)[3]),             \
                   "r"((b)[0]), "r"((b)[1]))

#define CP16(dst, src)                                                             \
    asm volatile("cp.async.cg.shared.global [%0], [%1], 16;" :: "r"(dst), "l"(src))
#define CP_COMMIT() asm volatile("cp.async.commit_group;" ::: "memory")
#define CP_WAIT(n)  asm volatile("cp.async.wait_group %0;" :: "n"(n) : "memory")

// ---------------- conversion kernels ----------------
__global__ void __launch_bounds__(256) convert_x_kernel(const float* __restrict__ x) {
    int gw = (blockIdx.x * 256 + threadIdx.x) >> 5;   // row
    int lane = threadIdx.x & 31;
    const float4* xr = reinterpret_cast<const float4*>(x + (size_t)gw * DIN);
    float s2 = 0.f;
    #pragma unroll
    for (int i = 0; i < 2; i++) {
        int q = lane + 32 * i;                        // float4 index 0..63
        float4 v = xr[q];
        s2 += v.x * v.x + v.y * v.y + v.z * v.z + v.w * v.w;
        __nv_bfloat16 h0 = __float2bfloat16(v.x), h1 = __float2bfloat16(v.y);
        __nv_bfloat16 h2 = __float2bfloat16(v.z), h3 = __float2bfloat16(v.w);
        __nv_bfloat16 l0 = __float2bfloat16(v.x - __bfloat162float(h0));
        __nv_bfloat16 l1 = __float2bfloat16(v.y - __bfloat162float(h1));
        __nv_bfloat16 l2 = __float2bfloat16(v.z - __bfloat162float(h2));
        __nv_bfloat16 l3 = __float2bfloat16(v.w - __bfloat162float(h3));
        __nv_bfloat162* dh = reinterpret_cast<__nv_bfloat162*>(g_xhi) + ((size_t)gw * DIN >> 1) + q * 2;
        __nv_bfloat162* dl = reinterpret_cast<__nv_bfloat162*>(g_xlo) + ((size_t)gw * DIN >> 1) + q * 2;
        __nv_bfloat162 th; th.x = h0; th.y = h1; dh[0] = th;
        th.x = h2; th.y = h3; dh[1] = th;
        __nv_bfloat162 tl; tl.x = l0; tl.y = l1; dl[0] = tl;
        tl.x = l2; tl.y = l3; dl[1] = tl;
    }
    s2 = wred(s2);
    if (lane == 0) g_xn2[gw] = s2;
}

__global__ void __launch_bounds__(256) convert_w_kernel(const float* __restrict__ W1,
                                                        const float* __restrict__ W2) {
    int i = blockIdx.x * 256 + threadIdx.x;
    if (i < DH * DIN) {
        float v = W1[i];
        __nv_bfloat16 h = __float2bfloat16(v);
        g_w1hi[i] = h;
        g_w1lo[i] = __float2bfloat16(v - __bfloat162float(h));
    }
    if (i < DOUT * DH) {
        float v = W2[i];
        __nv_bfloat16 h = __float2bfloat16(v);
        g_w2hi[i] = h;
        g_w2lo[i] = __float2bfloat16(v - __bfloat162float(h));
    }
}

// ---------------- mma.sync split-bf16 GEMM, cp.async 2-stage pipeline ----------------
// C[m,n] = sum_k A[m,k]*B[n,k], A ~ Ahi+Alo, B ~ Bhi+Blo (hi*hi + lo*hi + hi*lo).
// BM=128, BN=64, BK=32. 256 threads = 8 warps (4 in M x 2 in N), warp tile 32x32.
#define LDSP 40
#define A_TILE (128 * LDSP)     // elements
#define B_TILE (64 * LDSP)
#define STAGE_ELEMS (2 * A_TILE + 2 * B_TILE)   // Ahi, Alo, Bhi, Blo
#define GEMM_SMEM (2 * STAGE_ELEMS * 2)         // bytes (2 stages, bf16)

template<int K, int N>
__global__ void __launch_bounds__(256) mma_gemm(const __nv_bfloat16* __restrict__ Ahi,
                                                const __nv_bfloat16* __restrict__ Alo,
                                                const __nv_bfloat16* __restrict__ Bhi,
                                                const __nv_bfloat16* __restrict__ Blo,
                                                float* __restrict__ C)
{
    extern __shared__ __nv_bfloat16 smem[];
    const int tid = threadIdx.x, lane = tid & 31, wid = tid >> 5;
    const int warpM = wid & 3, warpN = wid >> 2;
    const int bm = blockIdx.y * 128, bn = blockIdx.x * 64;

    // per-stage base pointers (elements)
    // layout per stage: Ahi | Alo | Bhi | Blo
    const uint32_t sbase = smem_u32(smem);

    float acc[2][4][4];
    #pragma unroll
    for (int i = 0; i < 2; i++)
        #pragma unroll
        for (int j = 0; j < 4; j++)
            #pragma unroll
            for (int l = 0; l < 4; l++) acc[i][j][l] = 0.f;

    // cp.async addressing: A tiles 128x32 = 512 uint4 (2/thread), B 64x32 = 256 uint4 (1/thread)
    const int rA0 = tid >> 2, qA0 = (tid & 3) << 3;          // first A row/col
    const int rA1 = (tid + 256) >> 2, qA1 = qA0;             // second
    const int rB = tid >> 2, qB = (tid & 3) << 3;

    auto issue_stage = [&](int stage, int k0) {
        uint32_t st = sbase + stage * STAGE_ELEMS * 2;
        uint32_t dAhi = st, dAlo = st + A_TILE * 2;
        uint32_t dBhi = st + 2 * A_TILE * 2, dBlo = dBhi + B_TILE * 2;
        CP16(dAhi + (rA0 * LDSP + qA0) * 2, &Ahi[(size_t)(bm + rA0) * K + k0 + qA0]);
        CP16(dAhi + (rA1 * LDSP + qA1) * 2, &Ahi[(size_t)(bm + rA1) * K + k0 + qA1]);
        CP16(dAlo + (rA0 * LDSP + qA0) * 2, &Alo[(size_t)(bm + rA0) * K + k0 + qA0]);
        CP16(dAlo + (rA1 * LDSP + qA1) * 2, &Alo[(size_t)(bm + rA1) * K + k0 + qA1]);
        CP16(dBhi + (rB * LDSP + qB) * 2, &Bhi[(size_t)(bn + rB) * K + k0 + qB]);
        CP16(dBlo + (rB * LDSP + qB) * 2, &Blo[(size_t)(bn + rB) * K + k0 + qB]);
        CP_COMMIT();
    };

    // ldmatrix lane addressing
    const int rowA = (lane & 7) + ((lane >> 3) & 1) * 8;    // 0..15
    const int colA = ((lane >> 4) & 1) * 8;                 // 0 or 8
    const int rowB = warpN * 32 + ((lane >> 4) & 1) * 8 + (lane & 7);
    const int colB = ((lane >> 3) & 1) * 8;

    constexpr int NCHUNK = K / 32;
    issue_stage(0, 0);

    for (int ci = 0; ci < NCHUNK; ci++) {
        if (ci + 1 < NCHUNK) {
            issue_stage((ci + 1) & 1, (ci + 1) * 32);
            CP_WAIT(1);
        } else {
            CP_WAIT(0);
        }
        __syncthreads();

        uint32_t st = sbase + (ci & 1) * STAGE_ELEMS * 2;
        uint32_t uAhi = st, uAlo = st + A_TILE * 2;
        uint32_t uBhi = st + 2 * A_TILE * 2, uBlo = uBhi + B_TILE * 2;

        #pragma unroll
        for (int ks = 0; ks < 32; ks += 16) {
            uint32_t ahi[2][4], alo[2][4], bhi[4][2], blo[4][2];
            #pragma unroll
            for (int mt = 0; mt < 2; mt++) {
                uint32_t off = ((warpM * 32 + mt * 16 + rowA) * LDSP + colA + ks) * 2;
                LDSM4(ahi[mt][0], ahi[mt][1], ahi[mt][2], ahi[mt][3], uAhi + off);
                LDSM4(alo[mt][0], alo[mt][1], alo[mt][2], alo[mt][3], uAlo + off);
            }
            #pragma unroll
            for (int p = 0; p < 2; p++) {
                uint32_t off = ((rowB + p * 16) * LDSP + colB + ks) * 2;
                LDSM4(bhi[2 * p][0], bhi[2 * p][1], bhi[2 * p + 1][0], bhi[2 * p + 1][1], uBhi + off);
                LDSM4(blo[2 * p][0], blo[2 * p][1], blo[2 * p + 1][0], blo[2 * p + 1][1], uBlo + off);
            }
            #pragma unroll
            for (int mt = 0; mt < 2; mt++)
                #pragma unroll
                for (int nt = 0; nt < 4; nt++) {
                    MMA16816(acc[mt][nt], ahi[mt], bhi[nt]);
                    MMA16816(acc[mt][nt], alo[mt], bhi[nt]);
                    MMA16816(acc[mt][nt], ahi[mt], blo[nt]);
                }
        }
        __syncthreads();   // all warps done reading stage (ci&1) before it is rewritten
    }

    // writeout
    #pragma unroll
    for (int mt = 0; mt < 2; mt++) {
        int r0 = bm + warpM * 32 + mt * 16 + (lane >> 2);
        #pragma unroll
        for (int nt = 0; nt < 4; nt++) {
            int c = bn + warpN * 32 + nt * 8 + (lane & 3) * 2;
            float2 v0 = make_float2(acc[mt][nt][0], acc[mt][nt][1]);
            float2 v1 = make_float2(acc[mt][nt][2], acc[mt][nt][3]);
            *reinterpret_cast<float2*>(&C[(size_t)r0 * N + c]) = v0;
            *reinterpret_cast<float2*>(&C[(size_t)(r0 + 8) * N + c]) = v1;
        }
    }
}

// ---------------- layer-1 elementwise: warp per row, b1 in smem ----------------
__global__ void __launch_bounds__(256) ew1_warp(const float* __restrict__ b1) {
    __shared__ float sb1[DH];
    const int wid = threadIdx.x >> 5, lane = threadIdx.x & 31;
    for (int i = threadIdx.x; i < DH; i += 256) sb1[i] = b1[i];
    __syncthreads();

    const int row = blockIdx.x * 8 + wid;
    const float maxn = 1.0f - 4e-3f;
    const float* mx = g_c + (size_t)row * DH;

    float mv[16];
    const float4* m4 = reinterpret_cast<const float4*>(mx);
    float pm = 0.f, pvb = 0.f, py = 0.f;
    #pragma unroll
    for (int i = 0; i < 4; i++) {
        float4 a = m4[lane * 4 + i];
        mv[4 * i] = a.x; mv[4 * i + 1] = a.y; mv[4 * i + 2] = a.z; mv[4 * i + 3] = a.w;
        #pragma unroll
        for (int j = 0; j < 4; j++) {
            float b = sb1[lane * 16 + 4 * i + j];
            float m = mv[4 * i + j];
            pm  = fmaf(m, m, pm);
            pvb = fmaf(m, b, pvb);
            py  = fmaf(b, b, py);
        }
    }
    float mxn2 = wred(pm), vb = wred(pvb), y2 = wred(py);

    float xn  = fmaxf(sqrtf(g_xn2[row]), 1e-15f);
    float mxn = fmaxf(sqrtf(mxn2), 1e-15f);
    float ns  = tanh_fast(mxn / xn * artanh_fast(xn));
    float s   = ns / mxn;
    float f1  = ns > maxn ? maxn / ns : 1.f;
    float sc1 = s * f1;
    float ncl = fminf(ns, maxn);
    float x2  = ncl * ncl;
    float xy  = sc1 * vb;
    float den = fmaxf(1.f + 2.f * xy + x2 * y2, 1e-15f);
    float chv = (1.f + 2.f * xy + y2) / den;
    float cb  = (1.f - x2) / den;
    float al  = chv * sc1, be = cb;
    float np2 = al * al * mxn2 + 2.f * al * be * vb + be * be * y2;
    float np  = fmaxf(sqrtf(np2), 1e-15f);
    float f2  = np > maxn ? maxn / np : 1.f;
    float nn  = fminf(np, maxn);
    float gg  = artanh_fast(nn) / nn * f2;

    float w[16], pw = 0.f;
    #pragma unroll
    for (int i = 0; i < 16; i++) {
        w[i] = tanh_fast(gg * fmaf(al, mv[i], be * sb1[lane * 16 + i]));
        pw = fmaf(w[i], w[i], pw);
    }
    float wn2 = wred(pw);
    float wn = fmaxf(sqrtf(wn2), 1e-15f);
    float tn = tanh_fast(wn);
    float hc = fminf(tn, maxn);
    float e3 = hc / wn;
    if (lane == 0) g_hn2[row] = hc * hc;

    uint32_t ph[8], pl[8];
    #pragma unroll
    for (int i = 0; i < 8; i++) {
        float v0 = e3 * w[2 * i], v1 = e3 * w[2 * i + 1];
        __nv_bfloat16 h0 = __float2bfloat16(v0), h1 = __float2bfloat16(v1);
        __nv_bfloat16 l0 = __float2bfloat16(v0 - __bfloat162float(h0));
        __nv_bfloat16 l1 = __float2bfloat16(v1 - __bfloat162float(h1));
        ph[i] = (uint32_t)__bfloat16_as_ushort(h0) | ((uint32_t)__bfloat16_as_ushort(h1) << 16);
        pl[i] = (uint32_t)__bfloat16_as_ushort(l0) | ((uint32_t)__bfloat16_as_ushort(l1) << 16);
    }
    uint4* dh = reinterpret_cast<uint4*>(g_hhi + (size_t)row * DH + lane * 16);
    uint4* dl = reinterpret_cast<uint4*>(g_hlo + (size_t)row * DH + lane * 16);
    dh[0] = make_uint4(ph[0], ph[1], ph[2], ph[3]);
    dh[1] = make_uint4(ph[4], ph[5], ph[6], ph[7]);
    dl[0] = make_uint4(pl[0], pl[1], pl[2], pl[3]);
    dl[1] = make_uint4(pl[4], pl[5], pl[6], pl[7]);
}

// ---------------- layer-2 elementwise: warp per row ----------------
__global__ void __launch_bounds__(256) ew2_warp(const float* __restrict__ b2,
                                                float* __restrict__ out) {
    const int wid = threadIdx.x >> 5, lane = threadIdx.x & 31;
    const int row = blockIdx.x * 8 + wid;
    const float maxn = 1.0f - 4e-3f;
    const float* mx = g_c + (size_t)row * DOUT;

    float4 a = reinterpret_cast<const float4*>(mx)[lane];
    float4 b = reinterpret_cast<const float4*>(b2)[lane];
    float mv[4] = {a.x, a.y, a.z, a.w};
    float bv[4] = {b.x, b.y, b.z, b.w};
    float pm = 0.f, pvb = 0.f, py = 0.f;
    #pragma unroll
    for (int i = 0; i < 4; i++) {
        pm  = fmaf(mv[i], mv[i], pm);
        pvb = fmaf(mv[i], bv[i], pvb);
        py  = fmaf(bv[i], bv[i], py);
    }
    float mxn2 = wred(pm), vb = wred(pvb), y2 = wred(py);

    float xn  = fmaxf(sqrtf(g_hn2[row]), 1e-15f);
    float mxn = fmaxf(sqrtf(mxn2), 1e-15f);
    float ns  = tanh_fast(mxn / xn * artanh_fast(xn));
    float s   = ns / mxn;
    float f1  = ns > maxn ? maxn / ns : 1.f;
    float sc1 = s * f1;
    float ncl = fminf(ns, maxn);
    float x2  = ncl * ncl;
    float xy  = sc1 * vb;
    float den = fmaxf(1.f + 2.f * xy + x2 * y2, 1e-15f);
    float chv = (1.f + 2.f * xy + y2) / den;
    float cb  = (1.f - x2) / den;
    float al  = chv * sc1, be = cb;
    float np2 = al * al * mxn2 + 2.f * al * be * vb + be * be * y2;
    float np  = fmaxf(sqrtf(np2), 1e-15f);
    float f2  = np > maxn ? maxn / np : 1.f;

    float4 o;
    o.x = f2 * fmaf(al, mv[0], be * bv[0]);
    o.y = f2 * fmaf(al, mv[1], be * bv[1]);
    o.z = f2 * fmaf(al, mv[2], be * bv[2]);
    o.w = f2 * fmaf(al, mv[3], be * bv[3]);
    reinterpret_cast<float4*>(out + (size_t)row * DOUT)[lane] = o;
}

// ---------------- launch ----------------
extern "C" void kernel_launch(void* const* d_in, const int* in_sizes, int n_in,
                              void* d_out, int out_size) {
    const float* x  = (const float*)d_in[0];
    const float* W1 = (const float*)d_in[1];
    const float* b1 = (const float*)d_in[2];
    const float* W2 = (const float*)d_in[3];
    const float* b2 = (const float*)d_in[4];
    float* out = (float*)d_out;

    __nv_bfloat16 *xhi, *xlo, *w1hi, *w1lo, *w2hi, *w2lo, *hhi, *hlo;
    float* c;
    cudaGetSymbolAddress((void**)&xhi, g_xhi);
    cudaGetSymbolAddress((void**)&xlo, g_xlo);
    cudaGetSymbolAddress((void**)&w1hi, g_w1hi);
    cudaGetSymbolAddress((void**)&w1lo, g_w1lo);
    cudaGetSymbolAddress((void**)&w2hi, g_w2hi);
    cudaGetSymbolAddress((void**)&w2lo, g_w2lo);
    cudaGetSymbolAddress((void**)&hhi, g_hhi);
    cudaGetSymbolAddress((void**)&hlo, g_hlo);
    cudaGetSymbolAddress((void**)&c, g_c);

    cudaFuncSetAttribute(mma_gemm<DIN, DH>, cudaFuncAttributeMaxDynamicSharedMemorySize, GEMM_SMEM);
    cudaFuncSetAttribute(mma_gemm<DH, DOUT>, cudaFuncAttributeMaxDynamicSharedMemorySize, GEMM_SMEM);

    convert_x_kernel<<<BATCH / 8, 256>>>(x);
    convert_w_kernel<<<(DH * DIN + 255) / 256, 256>>>(W1, W2);

    // layer 1: mx1 = x @ W1^T  [B, 512]
    mma_gemm<DIN, DH><<<dim3(DH / 64, BATCH / 128), 256, GEMM_SMEM>>>(xhi, xlo, w1hi, w1lo, c);
    ew1_warp<<<BATCH / 8, 256>>>(b1);

    // layer 2: mx2 = h @ W2^T  [B, 128]
    mma_gemm<DH, DOUT><<<dim3(DOUT / 64, BATCH / 128), 256, GEMM_SMEM>>>(hhi, hlo, w2hi, w2lo, c);
    ew2_warp<<<BATCH / 8, 256>>>(b2, out);
}